// round 6
// baseline (speedup 1.0000x reference)
#include <cuda_runtime.h>
#include <cstddef>

#define Bn 128
#define Sn 512
#define Dn 256
#define Hn 512
#define On 256
#define NCTA 128

// ---------------------------------------------------------------------------
// Device scratch (static __device__ globals — the sanctioned no-alloc scratch)
// ---------------------------------------------------------------------------
__device__ __align__(16) float g_wx[(size_t)Bn * Sn * 4 * Hn];       // 512 MB  [b*S+s][4H]
__device__ __align__(16) float g_state[2 * Hn * Bn * 2];             // ping-pong, (h,c) interleaved, k-major
__device__ unsigned g_count = 0;
__device__ unsigned g_sense = 0;

// ---------------------------------------------------------------------------
// SGEMM with bias: C[M,N] = A[M,K] @ B[K,N] + bias[N]
// BM=BN=128, BK=16, 256 threads, 8x8 register tile. M,N mult of 128, K of 16.
// If C == nullptr, writes to g_wx.
// ---------------------------------------------------------------------------
__global__ void __launch_bounds__(256)
sgemm_bias(const float* __restrict__ A, const float* __restrict__ Bm,
           const float* __restrict__ bias, float* __restrict__ C,
           int M, int N, int K)
{
    if (C == nullptr) C = g_wx;

    __shared__ float As[16][132];   // [k][m]
    __shared__ float Bs[16][132];   // [k][n]

    const int tid = threadIdx.x;
    const int tx = tid & 15;
    const int ty = tid >> 4;
    const int m0 = blockIdx.y * 128;
    const int n0 = blockIdx.x * 128;

    float acc[8][8];
#pragma unroll
    for (int i = 0; i < 8; i++)
#pragma unroll
        for (int j = 0; j < 8; j++) acc[i][j] = 0.0f;

    const int ar = tid >> 1;            // A row in tile (0..127)
    const int ah = tid & 1;             // A k-half
    const float* Abase = A + (size_t)(m0 + ar) * K + ah * 8;
    const int bk = tid >> 5;            // B k row (0..7)
    const int bc = (tid & 31) * 4;      // B col quad

    for (int k0 = 0; k0 < K; k0 += 16) {
        float4 a0 = *reinterpret_cast<const float4*>(Abase + k0);
        float4 a1 = *reinterpret_cast<const float4*>(Abase + k0 + 4);
        As[ah * 8 + 0][ar] = a0.x; As[ah * 8 + 1][ar] = a0.y;
        As[ah * 8 + 2][ar] = a0.z; As[ah * 8 + 3][ar] = a0.w;
        As[ah * 8 + 4][ar] = a1.x; As[ah * 8 + 5][ar] = a1.y;
        As[ah * 8 + 6][ar] = a1.z; As[ah * 8 + 7][ar] = a1.w;
#pragma unroll
        for (int p = 0; p < 16; p += 8) {
            float4 bv = *reinterpret_cast<const float4*>(
                Bm + (size_t)(k0 + bk + p) * N + n0 + bc);
            *reinterpret_cast<float4*>(&Bs[bk + p][bc]) = bv;
        }
        __syncthreads();

#pragma unroll
        for (int k = 0; k < 16; k++) {
            float ra[8], rb[8];
            *reinterpret_cast<float4*>(ra)     = *reinterpret_cast<const float4*>(&As[k][ty * 8]);
            *reinterpret_cast<float4*>(ra + 4) = *reinterpret_cast<const float4*>(&As[k][ty * 8 + 4]);
            *reinterpret_cast<float4*>(rb)     = *reinterpret_cast<const float4*>(&Bs[k][tx * 8]);
            *reinterpret_cast<float4*>(rb + 4) = *reinterpret_cast<const float4*>(&Bs[k][tx * 8 + 4]);
#pragma unroll
            for (int i = 0; i < 8; i++)
#pragma unroll
                for (int j = 0; j < 8; j++)
                    acc[i][j] = fmaf(ra[i], rb[j], acc[i][j]);
        }
        __syncthreads();
    }

    float bb[8];
#pragma unroll
    for (int j = 0; j < 8; j++) bb[j] = bias[n0 + tx * 8 + j];

#pragma unroll
    for (int i = 0; i < 8; i++) {
        const size_t row = (size_t)(m0 + ty * 8 + i) * N + n0 + tx * 8;
        float4 o0, o1;
        o0.x = acc[i][0] + bb[0]; o0.y = acc[i][1] + bb[1];
        o0.z = acc[i][2] + bb[2]; o0.w = acc[i][3] + bb[3];
        o1.x = acc[i][4] + bb[4]; o1.y = acc[i][5] + bb[5];
        o1.z = acc[i][6] + bb[6]; o1.w = acc[i][7] + bb[7];
        *reinterpret_cast<float4*>(&C[row])     = o0;
        *reinterpret_cast<float4*>(&C[row + 4]) = o1;
    }
}

// ---------------------------------------------------------------------------
// Persistent recurrence
// ---------------------------------------------------------------------------
__device__ __forceinline__ float sigf(float x) { return 1.0f / (1.0f + __expf(-x)); }

__device__ __forceinline__ void grid_barrier(unsigned& lsense)
{
    __threadfence();                 // release own writes + CCTL.IVALL (L1 invalidate)
    __syncthreads();
    if (threadIdx.x == 0) {
        const unsigned target = lsense ^ 1u;
        if (atomicAdd(&g_count, 1u) == (unsigned)(NCTA - 1)) {
            g_count = 0;
            __threadfence();
            *((volatile unsigned*)&g_sense) = target;
        } else {
            while (*((volatile unsigned*)&g_sense) != target) { }
        }
    }
    __syncthreads();
    lsense ^= 1u;
}

#define GET(v, e) ((v).e)
#define DOT10(hv, E)                                                     \
    aF0 = fmaf((hv).x, GET(f0,E), aF0); aF1 = fmaf((hv).x, GET(f1,E), aF1); \
    aI0 = fmaf((hv).x, GET(i0,E), aI0); aI1 = fmaf((hv).x, GET(i1,E), aI1); \
    aO0 = fmaf((hv).x, GET(o0,E), aO0); aO1 = fmaf((hv).x, GET(o1,E), aO1); \
    aG0 = fmaf((hv).x, GET(q0,E), aG0); aG1 = fmaf((hv).x, GET(q1,E), aG1); \
    aD0 = fmaf((hv).y, GET(d0,E), aD0); aD1 = fmaf((hv).y, GET(d1,E), aD1);

__global__ void __launch_bounds__(256)
tlstm_recur(const float* __restrict__ U_all, const float* __restrict__ b_u,
            const float* __restrict__ W_d,  const float* __restrict__ b_d,
            const float* __restrict__ td,
            float* __restrict__ hs_out, float* __restrict__ cs_out)
{
    __shared__ float Us[4 * 4 * 512];   // [(jid*4+g)*512 + k], 32 KB
    __shared__ float Wds[4 * 512];      // [jid*512 + k],        8 KB

    const int tid = threadIdx.x;
    const int cid = blockIdx.x;
    const int b  = tid & 127;
    const int jp = tid >> 7;            // which j-pair (0/1)
    const int j0 = cid * 4 + jp * 2;    // first global hidden index of this thread

    // one-time: stage this CTA's weight columns into smem
    for (int i = tid; i < 8192; i += 256) {
        int k = i & 511, g = (i >> 9) & 3, jid = i >> 11;
        Us[i] = U_all[(size_t)k * 2048 + g * 512 + cid * 4 + jid];
    }
    for (int i = tid; i < 2048; i += 256) {
        int k = i & 511, jid = i >> 9;
        Wds[i] = W_d[(size_t)k * 512 + cid * 4 + jid];
    }

    float bu[8], bdv[2];
#pragma unroll
    for (int g = 0; g < 4; g++) {
        bu[g * 2 + 0] = b_u[g * 512 + j0];
        bu[g * 2 + 1] = b_u[g * 512 + j0 + 1];
    }
    bdv[0] = b_d[j0]; bdv[1] = b_d[j0 + 1];

    // zero ping buffer 0 (each CTA zeroes a disjoint 512-float2 slice)
    float2* stz = reinterpret_cast<float2*>(g_state);
    for (int i = tid; i < 512; i += 256)
        stz[cid * 512 + i] = make_float2(0.f, 0.f);

    unsigned lsense = *((volatile unsigned*)&g_sense);
    grid_barrier(lsense);

    const float4* U4 = reinterpret_cast<const float4*>(Us);
    const float4* W4 = reinterpret_cast<const float4*>(Wds);
    const int ub = jp * 1024;           // float4 base for jj=0 (jj=1 at +512)

    for (int s = 0; s < Sn; s++) {
        if (s) grid_barrier(lsense);

        const float2* st = reinterpret_cast<const float2*>(g_state) + (size_t)(s & 1) * (Hn * Bn);
        float2* stn      = reinterpret_cast<float2*>(g_state) + (size_t)((s & 1) ^ 1) * (Hn * Bn);

        // prefetch step operands (consumed after the 20k-cycle dot loop)
        const size_t wxb = ((size_t)b * Sn + s) * 2048;
        const float2 wxf = *reinterpret_cast<const float2*>(g_wx + wxb + 0 * 512 + j0);
        const float2 wxi = *reinterpret_cast<const float2*>(g_wx + wxb + 1 * 512 + j0);
        const float2 wxo = *reinterpret_cast<const float2*>(g_wx + wxb + 2 * 512 + j0);
        const float2 wxg = *reinterpret_cast<const float2*>(g_wx + wxb + 3 * 512 + j0);
        const float tdv  = td[(size_t)b * Sn + s];
        const float co0  = st[(size_t)j0 * 128 + b].y;
        const float co1  = st[(size_t)(j0 + 1) * 128 + b].y;

        float aF0=0.f,aF1=0.f,aI0=0.f,aI1=0.f,aO0=0.f,aO1=0.f,aG0=0.f,aG1=0.f,aD0=0.f,aD1=0.f;

#pragma unroll 2
        for (int k4 = 0; k4 < 128; k4++) {
            float2 h0v = st[(k4 * 4 + 0) * 128 + b];
            float2 h1v = st[(k4 * 4 + 1) * 128 + b];
            float2 h2v = st[(k4 * 4 + 2) * 128 + b];
            float2 h3v = st[(k4 * 4 + 3) * 128 + b];
            float4 f0 = U4[ub + 0 * 128 + k4];
            float4 i0 = U4[ub + 1 * 128 + k4];
            float4 o0 = U4[ub + 2 * 128 + k4];
            float4 q0 = U4[ub + 3 * 128 + k4];
            float4 f1 = U4[ub + 512 + 0 * 128 + k4];
            float4 i1 = U4[ub + 512 + 1 * 128 + k4];
            float4 o1 = U4[ub + 512 + 2 * 128 + k4];
            float4 q1 = U4[ub + 512 + 3 * 128 + k4];
            float4 d0 = W4[(jp * 2 + 0) * 128 + k4];
            float4 d1 = W4[(jp * 2 + 1) * 128 + k4];
            DOT10(h0v, x) DOT10(h1v, y) DOT10(h2v, z) DOT10(h3v, w)
        }

        // gates (jj = 0)
        float cst0  = sigf(aD0 + bdv[0]);
        float cadj0 = co0 - cst0 + cst0 * tdv;
        float ff0   = sigf(wxf.x + aF0 + bu[0]);
        float ii0   = sigf(wxi.x + aI0 + bu[2]);
        float oo0   = sigf(wxo.x + aO0 + bu[4]);
        float gg0   = tanhf(wxg.x + aG0 + bu[6]);
        float cn0   = ff0 * cadj0 + ii0 * gg0;
        float hn0   = oo0 * tanhf(cn0);
        // gates (jj = 1)
        float cst1  = sigf(aD1 + bdv[1]);
        float cadj1 = co1 - cst1 + cst1 * tdv;
        float ff1   = sigf(wxf.y + aF1 + bu[1]);
        float ii1   = sigf(wxi.y + aI1 + bu[3]);
        float oo1   = sigf(wxo.y + aO1 + bu[5]);
        float gg1   = tanhf(wxg.y + aG1 + bu[7]);
        float cn1   = ff1 * cadj1 + ii1 * gg1;
        float hn1   = oo1 * tanhf(cn1);

        stn[(size_t)j0 * 128 + b]       = make_float2(hn0, cn0);
        stn[(size_t)(j0 + 1) * 128 + b] = make_float2(hn1, cn1);

        const size_t ob = ((size_t)b * Sn + s) * Hn + j0;
        *reinterpret_cast<float2*>(hs_out + ob) = make_float2(hn0, hn1);
        *reinterpret_cast<float2*>(cs_out + ob) = make_float2(cn0, cn1);
    }
}

// ---------------------------------------------------------------------------
// Launch
// ---------------------------------------------------------------------------
extern "C" void kernel_launch(void* const* d_in, const int* in_sizes, int n_in,
                              void* d_out, int out_size)
{
    const float* inputs     = (const float*)d_in[0];
    const float* time_diffs = (const float*)d_in[1];
    // d_in[2] = seq_lens (unused by reference)
    const float* W_all      = (const float*)d_in[3];
    const float* b_all      = (const float*)d_in[4];
    const float* U_all      = (const float*)d_in[5];
    const float* b_u        = (const float*)d_in[6];
    const float* W_d        = (const float*)d_in[7];
    const float* b_d        = (const float*)d_in[8];
    const float* W_out      = (const float*)d_in[9];
    const float* b_out      = (const float*)d_in[10];

    float* out = (float*)d_out;                        // [B,S,O]
    float* hs  = out + (size_t)Bn * Sn * On;           // [B,S,H]
    float* cs  = hs  + (size_t)Bn * Sn * Hn;           // [B,S,H]

    const int M = Bn * Sn;  // 65536

    // GEMM1: Wx = inputs @ W_all + b_all  -> g_wx (C == nullptr sentinel)
    {
        dim3 grid((4 * Hn) / 128, M / 128);
        sgemm_bias<<<grid, 256>>>(inputs, W_all, b_all, nullptr, M, 4 * Hn, Dn);
    }

    // Recurrence: 512 steps, persistent grid
    tlstm_recur<<<NCTA, 256>>>(U_all, b_u, W_d, b_d, time_diffs, hs, cs);

    // GEMM2: outputs = hs @ W_out + b_out
    {
        dim3 grid(On / 128, M / 128);
        sgemm_bias<<<grid, 256>>>(hs, W_out, b_out, out, M, On, Hn);
    }
}

// round 7
// speedup vs baseline: 1.8104x; 1.8104x over previous
#include <cuda_runtime.h>
#include <cstddef>

#define Bn 128
#define Sn 512
#define Dn 256
#define Hn 512
#define On 256
#define NCTA 128

// ---------------------------------------------------------------------------
// Device scratch (static __device__ globals — the sanctioned no-alloc scratch)
// ---------------------------------------------------------------------------
__device__ __align__(16) float g_wx[(size_t)Bn * Sn * 4 * Hn];   // [b*S+s][4H]
__device__ __align__(16) float g_state[2 * Hn * Bn * 2];         // ping-pong, float2(h,c), k-major
__device__ unsigned g_count = 0;
__device__ unsigned g_sense = 0;

// ---------------------------------------------------------------------------
// SGEMM with bias: C[M,N] = A[M,K] @ B[K,N] + bias[N]   (unchanged, passing)
// ---------------------------------------------------------------------------
__global__ void __launch_bounds__(256)
sgemm_bias(const float* __restrict__ A, const float* __restrict__ Bm,
           const float* __restrict__ bias, float* __restrict__ C,
           int M, int N, int K)
{
    if (C == nullptr) C = g_wx;

    __shared__ float As[16][132];
    __shared__ float Bs[16][132];

    const int tid = threadIdx.x;
    const int tx = tid & 15;
    const int ty = tid >> 4;
    const int m0 = blockIdx.y * 128;
    const int n0 = blockIdx.x * 128;

    float acc[8][8];
#pragma unroll
    for (int i = 0; i < 8; i++)
#pragma unroll
        for (int j = 0; j < 8; j++) acc[i][j] = 0.0f;

    const int ar = tid >> 1;
    const int ah = tid & 1;
    const float* Abase = A + (size_t)(m0 + ar) * K + ah * 8;
    const int bk = tid >> 5;
    const int bc = (tid & 31) * 4;

    for (int k0 = 0; k0 < K; k0 += 16) {
        float4 a0 = *reinterpret_cast<const float4*>(Abase + k0);
        float4 a1 = *reinterpret_cast<const float4*>(Abase + k0 + 4);
        As[ah * 8 + 0][ar] = a0.x; As[ah * 8 + 1][ar] = a0.y;
        As[ah * 8 + 2][ar] = a0.z; As[ah * 8 + 3][ar] = a0.w;
        As[ah * 8 + 4][ar] = a1.x; As[ah * 8 + 5][ar] = a1.y;
        As[ah * 8 + 6][ar] = a1.z; As[ah * 8 + 7][ar] = a1.w;
#pragma unroll
        for (int p = 0; p < 16; p += 8) {
            float4 bv = *reinterpret_cast<const float4*>(
                Bm + (size_t)(k0 + bk + p) * N + n0 + bc);
            *reinterpret_cast<float4*>(&Bs[bk + p][bc]) = bv;
        }
        __syncthreads();

#pragma unroll
        for (int k = 0; k < 16; k++) {
            float ra[8], rb[8];
            *reinterpret_cast<float4*>(ra)     = *reinterpret_cast<const float4*>(&As[k][ty * 8]);
            *reinterpret_cast<float4*>(ra + 4) = *reinterpret_cast<const float4*>(&As[k][ty * 8 + 4]);
            *reinterpret_cast<float4*>(rb)     = *reinterpret_cast<const float4*>(&Bs[k][tx * 8]);
            *reinterpret_cast<float4*>(rb + 4) = *reinterpret_cast<const float4*>(&Bs[k][tx * 8 + 4]);
#pragma unroll
            for (int i = 0; i < 8; i++)
#pragma unroll
                for (int j = 0; j < 8; j++)
                    acc[i][j] = fmaf(ra[i], rb[j], acc[i][j]);
        }
        __syncthreads();
    }

    float bb[8];
#pragma unroll
    for (int j = 0; j < 8; j++) bb[j] = bias[n0 + tx * 8 + j];

#pragma unroll
    for (int i = 0; i < 8; i++) {
        const size_t row = (size_t)(m0 + ty * 8 + i) * N + n0 + tx * 8;
        float4 o0, o1;
        o0.x = acc[i][0] + bb[0]; o0.y = acc[i][1] + bb[1];
        o0.z = acc[i][2] + bb[2]; o0.w = acc[i][3] + bb[3];
        o1.x = acc[i][4] + bb[4]; o1.y = acc[i][5] + bb[5];
        o1.z = acc[i][6] + bb[6]; o1.w = acc[i][7] + bb[7];
        *reinterpret_cast<float4*>(&C[row])     = o0;
        *reinterpret_cast<float4*>(&C[row + 4]) = o1;
    }
}

// ---------------------------------------------------------------------------
// f32x2 packed helpers (sm_103a)
// ---------------------------------------------------------------------------
__device__ __forceinline__ unsigned long long pack2(float v) {
    unsigned long long r;
    asm("mov.b64 %0, {%1, %1};" : "=l"(r) : "f"(v));
    return r;
}
__device__ __forceinline__ void fma2(unsigned long long& d,
                                     unsigned long long a, unsigned long long b) {
    asm("fma.rn.f32x2 %0, %1, %2, %0;" : "+l"(d) : "l"(a), "l"(b));
}
__device__ __forceinline__ float2 unpack2(unsigned long long v) {
    float2 r;
    asm("mov.b64 {%0, %1}, %2;" : "=f"(r.x), "=f"(r.y) : "l"(v));
    return r;
}

__device__ __forceinline__ float sigf(float x) { return 1.0f / (1.0f + __expf(-x)); }

__device__ __forceinline__ void grid_barrier(unsigned& lsense)
{
    __threadfence();
    __syncthreads();
    if (threadIdx.x == 0) {
        const unsigned target = lsense ^ 1u;
        if (atomicAdd(&g_count, 1u) == (unsigned)(NCTA - 1)) {
            g_count = 0;
            __threadfence();
            *((volatile unsigned*)&g_sense) = target;
        } else {
            while (*((volatile unsigned*)&g_sense) != target) { }
        }
    }
    __syncthreads();
    lsense ^= 1u;
}

// ---------------------------------------------------------------------------
// Persistent recurrence: 128 CTAs x 256 threads.
// CTA cid owns hidden columns j = cid*4 .. cid*4+3.
// Thread = (b = tid&127, kg = tid>>7). Each thread computes ALL 4 j over its
// half of K (256 k) with f32x2-packed FMAs (j-pairs in the two lanes).
// Weights live in SMEM, pre-packed as {w(k,j0),w(k,j1)} pairs.
// ---------------------------------------------------------------------------
__global__ void __launch_bounds__(256, 1)
tlstm_recur(const float* __restrict__ U_all, const float* __restrict__ b_u,
            const float* __restrict__ W_d,  const float* __restrict__ b_d,
            const float* __restrict__ td,
            float* __restrict__ hs_out, float* __restrict__ cs_out)
{
    extern __shared__ unsigned long long smem_u[];
    unsigned long long* Us2 = smem_u;          // [ (g*2+p)*256 + kp ] x {k-even, k-odd} : 4096 ull
    unsigned long long* Wd2 = smem_u + 4096;   // [ p*256 + kp ] x {k-even, k-odd}       : 1024 ull
    float* red  = (float*)(smem_u + 5120);     // [b][20] partials : 2560 floats
    float* bu_s = red + 2560;                  // [g*4 + j] : 16
    float* bd_s = bu_s + 16;                   // [j] : 4

    const int tid = threadIdx.x;
    const int cid = blockIdx.x;
    const int b   = tid & 127;
    const int kg  = tid >> 7;          // which K-half

    // ---- one-time staging: packed weight pairs into SMEM ----
    {
        float* UsF = (float*)Us2;
        for (int i = tid; i < 8192; i += 256) {
            const int jj = i & 1;
            const int h  = (i >> 1) & 1;
            const int kp = (i >> 2) & 255;
            const int p  = (i >> 10) & 1;
            const int g  = i >> 11;
            const int k  = kp * 2 + h;
            UsF[i] = U_all[(size_t)k * 2048 + g * 512 + cid * 4 + p * 2 + jj];
        }
        float* WdF = (float*)Wd2;
        for (int i = tid; i < 2048; i += 256) {
            const int jj = i & 1;
            const int h  = (i >> 1) & 1;
            const int kp = (i >> 2) & 255;
            const int p  = i >> 10;
            const int k  = kp * 2 + h;
            WdF[i] = W_d[(size_t)k * 512 + cid * 4 + p * 2 + jj];
        }
        if (tid < 16) bu_s[tid] = b_u[(tid >> 2) * 512 + cid * 4 + (tid & 3)];
        if (tid < 4)  bd_s[tid] = b_d[cid * 4 + tid];
    }

    // zero ping buffer 0 (disjoint slice per CTA)
    {
        float2* stz = reinterpret_cast<float2*>(g_state);
        for (int i = tid; i < 512; i += 256)
            stz[cid * 512 + i] = make_float2(0.f, 0.f);
    }

    unsigned lsense = *((volatile unsigned*)&g_sense);
    grid_barrier(lsense);

    const int kp0 = kg * 128;
    const int kpE = kp0 + 128;

    for (int s = 0; s < Sn; s++) {
        if (s) grid_barrier(lsense);

        const float2* st = reinterpret_cast<const float2*>(g_state) + (size_t)(s & 1) * (Hn * Bn);
        float2*      stn = reinterpret_cast<float2*>(g_state) + (size_t)((s & 1) ^ 1) * (Hn * Bn);

        // ---- prefetch step operands (consumed after the dot loop) ----
        const float* wxb = g_wx + ((size_t)b * Sn + s) * 2048 + cid * 4;
        float wxa[4][4];
#pragma unroll
        for (int g = 0; g < 4; g++) {
            float4 v = __ldg(reinterpret_cast<const float4*>(wxb + g * 512));
            wxa[g][0] = v.x; wxa[g][1] = v.y; wxa[g][2] = v.z; wxa[g][3] = v.w;
        }
        float c_old[4];
#pragma unroll
        for (int j = 0; j < 4; j++)
            c_old[j] = __ldcg(st + (size_t)(cid * 4 + j) * 128 + b).y;
        const float tdv = __ldg(td + (size_t)b * Sn + s);

        // ---- dot products over this thread's K-half ----
        unsigned long long acc[10];
#pragma unroll
        for (int i = 0; i < 10; i++) acc[i] = 0ull;

        float2 s0 = __ldcg(st + (size_t)(2 * kp0) * 128 + b);
        float2 s1 = __ldcg(st + (size_t)(2 * kp0 + 1) * 128 + b);

#pragma unroll 2
        for (int kp = kp0; kp < kpE; kp++) {
            const float2 cur0 = s0, cur1 = s1;
            const int nk = (kp + 1 < kpE) ? kp + 1 : kp;     // clamped prefetch
            s0 = __ldcg(st + (size_t)(2 * nk) * 128 + b);
            s1 = __ldcg(st + (size_t)(2 * nk + 1) * 128 + b);

            const unsigned long long hh0 = pack2(cur0.x);
            const unsigned long long cc0 = pack2(cur0.y);
            const unsigned long long hh1 = pack2(cur1.x);
            const unsigned long long cc1 = pack2(cur1.y);

#pragma unroll
            for (int g = 0; g < 4; g++) {
#pragma unroll
                for (int p = 0; p < 2; p++) {
                    ulonglong2 w = *reinterpret_cast<const ulonglong2*>(
                        Us2 + (size_t)(((g * 2 + p) * 256 + kp) * 2));
                    fma2(acc[g * 2 + p], hh0, w.x);
                    fma2(acc[g * 2 + p], hh1, w.y);
                }
            }
#pragma unroll
            for (int p = 0; p < 2; p++) {
                ulonglong2 w = *reinterpret_cast<const ulonglong2*>(
                    Wd2 + (size_t)((p * 256 + kp) * 2));
                fma2(acc[8 + p], cc0, w.x);
                fma2(acc[8 + p], cc1, w.y);
            }
        }

        // ---- reduce the two K-halves via SMEM ----
        if (kg == 1) {
#pragma unroll
            for (int i = 0; i < 10; i++) {
                float2 r = unpack2(acc[i]);
                red[b * 20 + i * 2]     = r.x;
                red[b * 20 + i * 2 + 1] = r.y;
            }
        }
        __syncthreads();

        if (kg == 0) {
            float G[5][4];
#pragma unroll
            for (int i = 0; i < 10; i++) {
                float2 mine = unpack2(acc[i]);
                const int g = i >> 1;
                const int p = i & 1;
                G[g][p * 2 + 0] = mine.x + red[b * 20 + i * 2];
                G[g][p * 2 + 1] = mine.y + red[b * 20 + i * 2 + 1];
            }

            float hv[4], cv[4];
#pragma unroll
            for (int j = 0; j < 4; j++) {
                const float cst  = sigf(G[4][j] + bd_s[j]);
                const float cadj = c_old[j] - cst + cst * tdv;
                const float ff   = sigf(wxa[0][j] + G[0][j] + bu_s[j]);
                const float ii   = sigf(wxa[1][j] + G[1][j] + bu_s[4 + j]);
                const float oo   = sigf(wxa[2][j] + G[2][j] + bu_s[8 + j]);
                const float gg   = tanhf(wxa[3][j] + G[3][j] + bu_s[12 + j]);
                const float cn   = ff * cadj + ii * gg;
                const float hn   = oo * tanhf(cn);
                cv[j] = cn; hv[j] = hn;
                stn[(size_t)(cid * 4 + j) * 128 + b] = make_float2(hn, cn);
            }

            const size_t ob = ((size_t)b * Sn + s) * Hn + cid * 4;
            *reinterpret_cast<float4*>(hs_out + ob) = make_float4(hv[0], hv[1], hv[2], hv[3]);
            *reinterpret_cast<float4*>(cs_out + ob) = make_float4(cv[0], cv[1], cv[2], cv[3]);
        }
    }
}

// ---------------------------------------------------------------------------
// Launch
// ---------------------------------------------------------------------------
extern "C" void kernel_launch(void* const* d_in, const int* in_sizes, int n_in,
                              void* d_out, int out_size)
{
    const float* inputs     = (const float*)d_in[0];
    const float* time_diffs = (const float*)d_in[1];
    // d_in[2] = seq_lens (unused by reference)
    const float* W_all      = (const float*)d_in[3];
    const float* b_all      = (const float*)d_in[4];
    const float* U_all      = (const float*)d_in[5];
    const float* b_u        = (const float*)d_in[6];
    const float* W_d        = (const float*)d_in[7];
    const float* b_d        = (const float*)d_in[8];
    const float* W_out      = (const float*)d_in[9];
    const float* b_out      = (const float*)d_in[10];

    float* out = (float*)d_out;                        // [B,S,O]
    float* hs  = out + (size_t)Bn * Sn * On;           // [B,S,H]
    float* cs  = hs  + (size_t)Bn * Sn * Hn;           // [B,S,H]

    const int M = Bn * Sn;  // 65536

    // GEMM1: Wx = inputs @ W_all + b_all  -> g_wx
    {
        dim3 grid((4 * Hn) / 128, M / 128);
        sgemm_bias<<<grid, 256>>>(inputs, W_all, b_all, nullptr, M, 4 * Hn, Dn);
    }

    // Recurrence: persistent grid, grid-wide barrier per step
    {
        const int shmem = 5120 * 8 + 2560 * 4 + 20 * 4;  // 51280 B
        cudaFuncSetAttribute(tlstm_recur,
                             cudaFuncAttributeMaxDynamicSharedMemorySize, shmem);
        tlstm_recur<<<NCTA, 256, shmem>>>(U_all, b_u, W_d, b_d, time_diffs, hs, cs);
    }

    // GEMM2: outputs = hs @ W_out + b_out
    {
        dim3 grid(On / 128, M / 128);
        sgemm_bias<<<grid, 256>>>(hs, W_out, b_out, out, M, On, Hn);
    }
}

// round 8
// speedup vs baseline: 2.4742x; 1.3667x over previous
#include <cuda_runtime.h>
#include <cstddef>

#define Bn 128
#define Sn 512
#define Dn 256
#define Hn 512
#define On 256
#define NCTA 128

// ---------------------------------------------------------------------------
// Device scratch (static __device__ globals — the sanctioned no-alloc scratch)
// ---------------------------------------------------------------------------
__device__ __align__(16) float g_wx[(size_t)Bn * Sn * 4 * Hn];   // [b*S+s][4H]
__device__ __align__(16) float g_state[2 * Hn * Bn * 2];         // ping-pong, float2(h,c), k-major
__device__ unsigned g_count = 0;
__device__ unsigned g_sense = 0;

// ---------------------------------------------------------------------------
// SGEMM with bias: C[M,N] = A[M,K] @ B[K,N] + bias[N]   (unchanged, passing)
// ---------------------------------------------------------------------------
__global__ void __launch_bounds__(256)
sgemm_bias(const float* __restrict__ A, const float* __restrict__ Bm,
           const float* __restrict__ bias, float* __restrict__ C,
           int M, int N, int K)
{
    if (C == nullptr) C = g_wx;

    __shared__ float As[16][132];
    __shared__ float Bs[16][132];

    const int tid = threadIdx.x;
    const int tx = tid & 15;
    const int ty = tid >> 4;
    const int m0 = blockIdx.y * 128;
    const int n0 = blockIdx.x * 128;

    float acc[8][8];
#pragma unroll
    for (int i = 0; i < 8; i++)
#pragma unroll
        for (int j = 0; j < 8; j++) acc[i][j] = 0.0f;

    const int ar = tid >> 1;
    const int ah = tid & 1;
    const float* Abase = A + (size_t)(m0 + ar) * K + ah * 8;
    const int bk = tid >> 5;
    const int bc = (tid & 31) * 4;

    for (int k0 = 0; k0 < K; k0 += 16) {
        float4 a0 = *reinterpret_cast<const float4*>(Abase + k0);
        float4 a1 = *reinterpret_cast<const float4*>(Abase + k0 + 4);
        As[ah * 8 + 0][ar] = a0.x; As[ah * 8 + 1][ar] = a0.y;
        As[ah * 8 + 2][ar] = a0.z; As[ah * 8 + 3][ar] = a0.w;
        As[ah * 8 + 4][ar] = a1.x; As[ah * 8 + 5][ar] = a1.y;
        As[ah * 8 + 6][ar] = a1.z; As[ah * 8 + 7][ar] = a1.w;
#pragma unroll
        for (int p = 0; p < 16; p += 8) {
            float4 bv = *reinterpret_cast<const float4*>(
                Bm + (size_t)(k0 + bk + p) * N + n0 + bc);
            *reinterpret_cast<float4*>(&Bs[bk + p][bc]) = bv;
        }
        __syncthreads();

#pragma unroll
        for (int k = 0; k < 16; k++) {
            float ra[8], rb[8];
            *reinterpret_cast<float4*>(ra)     = *reinterpret_cast<const float4*>(&As[k][ty * 8]);
            *reinterpret_cast<float4*>(ra + 4) = *reinterpret_cast<const float4*>(&As[k][ty * 8 + 4]);
            *reinterpret_cast<float4*>(rb)     = *reinterpret_cast<const float4*>(&Bs[k][tx * 8]);
            *reinterpret_cast<float4*>(rb + 4) = *reinterpret_cast<const float4*>(&Bs[k][tx * 8 + 4]);
#pragma unroll
            for (int i = 0; i < 8; i++)
#pragma unroll
                for (int j = 0; j < 8; j++)
                    acc[i][j] = fmaf(ra[i], rb[j], acc[i][j]);
        }
        __syncthreads();
    }

    float bb[8];
#pragma unroll
    for (int j = 0; j < 8; j++) bb[j] = bias[n0 + tx * 8 + j];

#pragma unroll
    for (int i = 0; i < 8; i++) {
        const size_t row = (size_t)(m0 + ty * 8 + i) * N + n0 + tx * 8;
        float4 o0, o1;
        o0.x = acc[i][0] + bb[0]; o0.y = acc[i][1] + bb[1];
        o0.z = acc[i][2] + bb[2]; o0.w = acc[i][3] + bb[3];
        o1.x = acc[i][4] + bb[4]; o1.y = acc[i][5] + bb[5];
        o1.z = acc[i][6] + bb[6]; o1.w = acc[i][7] + bb[7];
        *reinterpret_cast<float4*>(&C[row])     = o0;
        *reinterpret_cast<float4*>(&C[row + 4]) = o1;
    }
}

// ---------------------------------------------------------------------------
// f32x2 packed helpers (sm_103a)
// ---------------------------------------------------------------------------
__device__ __forceinline__ unsigned long long pack2(float v) {
    unsigned long long r;
    asm("mov.b64 %0, {%1, %1};" : "=l"(r) : "f"(v));
    return r;
}
__device__ __forceinline__ void fma2(unsigned long long& d,
                                     unsigned long long a, unsigned long long b) {
    asm("fma.rn.f32x2 %0, %1, %2, %0;" : "+l"(d) : "l"(a), "l"(b));
}
__device__ __forceinline__ float2 unpack2(unsigned long long v) {
    float2 r;
    asm("mov.b64 {%0, %1}, %2;" : "=f"(r.x), "=f"(r.y) : "l"(v));
    return r;
}

__device__ __forceinline__ float sigf(float x) { return 1.0f / (1.0f + __expf(-x)); }

__device__ __forceinline__ void grid_barrier(unsigned& lsense)
{
    __threadfence();
    __syncthreads();
    if (threadIdx.x == 0) {
        const unsigned target = lsense ^ 1u;
        if (atomicAdd(&g_count, 1u) == (unsigned)(NCTA - 1)) {
            g_count = 0;
            __threadfence();
            *((volatile unsigned*)&g_sense) = target;
        } else {
            while (*((volatile unsigned*)&g_sense) != target) { }
        }
    }
    __syncthreads();
    lsense ^= 1u;
}

// ---------------------------------------------------------------------------
// Persistent recurrence: 128 CTAs x 256 threads.
// CTA cid owns hidden columns j = cid*4 .. cid*4+3.
// Thread = (b = tid&127, kg = tid>>7) computes all 4 j over its K-half with
// f32x2-packed FMAs. State loads are chunked + double-buffered (MLP=16) so
// the ~300-cycle L2 latency is fully covered by each chunk's 160 FFMA2s.
// ---------------------------------------------------------------------------

// Load one 16-k chunk of state (float2 h,c per k) into a register buffer.
#define LOAD_CHUNK(BUF, CH) do {                                          \
    const int kn_ = kb0 + (CH) * 16;                                      \
    _Pragma("unroll")                                                     \
    for (int i_ = 0; i_ < 16; i_++)                                       \
        BUF[i_] = __ldcg(st + (size_t)(kn_ + i_) * 128 + b);              \
} while (0)

// Consume one 16-k chunk: 8 k-pairs x 20 fma2.
#define COMPUTE_CHUNK(BUF, CH) do {                                       \
    _Pragma("unroll")                                                     \
    for (int t_ = 0; t_ < 8; t_++) {                                      \
        const int kp_ = kp0 + (CH) * 8 + t_;                              \
        const unsigned long long hh0 = pack2(BUF[2 * t_].x);              \
        const unsigned long long cc0 = pack2(BUF[2 * t_].y);              \
        const unsigned long long hh1 = pack2(BUF[2 * t_ + 1].x);          \
        const unsigned long long cc1 = pack2(BUF[2 * t_ + 1].y);          \
        _Pragma("unroll")                                                 \
        for (int g_ = 0; g_ < 4; g_++) {                                  \
            _Pragma("unroll")                                             \
            for (int p_ = 0; p_ < 2; p_++) {                              \
                ulonglong2 w = *reinterpret_cast<const ulonglong2*>(      \
                    Us2 + (size_t)(((g_ * 2 + p_) * 256 + kp_) * 2));     \
                fma2(acc[g_ * 2 + p_], hh0, w.x);                         \
                fma2(acc[g_ * 2 + p_], hh1, w.y);                         \
            }                                                             \
        }                                                                 \
        _Pragma("unroll")                                                 \
        for (int p_ = 0; p_ < 2; p_++) {                                  \
            ulonglong2 w = *reinterpret_cast<const ulonglong2*>(          \
                Wd2 + (size_t)((p_ * 256 + kp_) * 2));                    \
            fma2(acc[8 + p_], cc0, w.x);                                  \
            fma2(acc[8 + p_], cc1, w.y);                                  \
        }                                                                 \
    }                                                                     \
} while (0)

__global__ void __launch_bounds__(256, 1)
tlstm_recur(const float* __restrict__ U_all, const float* __restrict__ b_u,
            const float* __restrict__ W_d,  const float* __restrict__ b_d,
            const float* __restrict__ td,
            float* __restrict__ hs_out, float* __restrict__ cs_out)
{
    extern __shared__ unsigned long long smem_u[];
    unsigned long long* Us2 = smem_u;          // [ (g*2+p)*256 + kp ] x {k-even,k-odd} : 4096 ull
    unsigned long long* Wd2 = smem_u + 4096;   // [ p*256 + kp ] x {k-even,k-odd}       : 1024 ull
    float* red  = (float*)(smem_u + 5120);     // [b][20] partials : 2560 floats
    float* bu_s = red + 2560;                  // [g*4 + j] : 16
    float* bd_s = bu_s + 16;                   // [j] : 4

    const int tid = threadIdx.x;
    const int cid = blockIdx.x;
    const int b   = tid & 127;
    const int kg  = tid >> 7;          // which K-half

    // ---- one-time staging: packed weight pairs into SMEM ----
    {
        float* UsF = (float*)Us2;
        for (int i = tid; i < 8192; i += 256) {
            const int jj = i & 1;
            const int h  = (i >> 1) & 1;
            const int kp = (i >> 2) & 255;
            const int p  = (i >> 10) & 1;
            const int g  = i >> 11;
            const int k  = kp * 2 + h;
            UsF[i] = U_all[(size_t)k * 2048 + g * 512 + cid * 4 + p * 2 + jj];
        }
        float* WdF = (float*)Wd2;
        for (int i = tid; i < 2048; i += 256) {
            const int jj = i & 1;
            const int h  = (i >> 1) & 1;
            const int kp = (i >> 2) & 255;
            const int p  = i >> 10;
            const int k  = kp * 2 + h;
            WdF[i] = W_d[(size_t)k * 512 + cid * 4 + p * 2 + jj];
        }
        if (tid < 16) bu_s[tid] = b_u[(tid >> 2) * 512 + cid * 4 + (tid & 3)];
        if (tid < 4)  bd_s[tid] = b_d[cid * 4 + tid];
    }

    // zero ping buffer 0 (disjoint slice per CTA)
    {
        float2* stz = reinterpret_cast<float2*>(g_state);
        for (int i = tid; i < 512; i += 256)
            stz[cid * 512 + i] = make_float2(0.f, 0.f);
    }

    unsigned lsense = *((volatile unsigned*)&g_sense);
    grid_barrier(lsense);

    const int kp0 = kg * 128;          // first k-pair of this thread's half
    const int kb0 = kp0 * 2;           // first k

    for (int s = 0; s < Sn; s++) {
        if (s) grid_barrier(lsense);

        const float2* st = reinterpret_cast<const float2*>(g_state) + (size_t)(s & 1) * (Hn * Bn);
        float2*      stn = reinterpret_cast<float2*>(g_state) + (size_t)((s & 1) ^ 1) * (Hn * Bn);

        // ---- prefetch step operands (consumed after the dot loop) ----
        const float* wxb = g_wx + ((size_t)b * Sn + s) * 2048 + cid * 4;
        float wxa[4][4];
#pragma unroll
        for (int g = 0; g < 4; g++) {
            float4 v = __ldg(reinterpret_cast<const float4*>(wxb + g * 512));
            wxa[g][0] = v.x; wxa[g][1] = v.y; wxa[g][2] = v.z; wxa[g][3] = v.w;
        }
        float c_old[4];
#pragma unroll
        for (int j = 0; j < 4; j++)
            c_old[j] = __ldcg(st + (size_t)(cid * 4 + j) * 128 + b).y;
        const float tdv = __ldg(td + (size_t)b * Sn + s);

        // ---- dot products over this thread's K-half (chunked, MLP=16) ----
        unsigned long long acc[10];
#pragma unroll
        for (int i = 0; i < 10; i++) acc[i] = 0ull;

        float2 bufA[16], bufB[16];
        LOAD_CHUNK(bufA, 0);

#pragma unroll 1
        for (int ch = 0; ch < 16; ch += 2) {
            LOAD_CHUNK(bufB, ch + 1);
            COMPUTE_CHUNK(bufA, ch);
            if (ch + 2 < 16) LOAD_CHUNK(bufA, ch + 2);
            COMPUTE_CHUNK(bufB, ch + 1);
        }

        // ---- reduce the two K-halves via SMEM ----
        if (kg == 1) {
#pragma unroll
            for (int i = 0; i < 10; i++) {
                float2 r = unpack2(acc[i]);
                red[b * 20 + i * 2]     = r.x;
                red[b * 20 + i * 2 + 1] = r.y;
            }
        }
        __syncthreads();

        if (kg == 0) {
            float G[5][4];
#pragma unroll
            for (int i = 0; i < 10; i++) {
                float2 mine = unpack2(acc[i]);
                const int g = i >> 1;
                const int p = i & 1;
                G[g][p * 2 + 0] = mine.x + red[b * 20 + i * 2];
                G[g][p * 2 + 1] = mine.y + red[b * 20 + i * 2 + 1];
            }

            float hv[4], cv[4];
#pragma unroll
            for (int j = 0; j < 4; j++) {
                const float cst  = sigf(G[4][j] + bd_s[j]);
                const float cadj = c_old[j] - cst + cst * tdv;
                const float ff   = sigf(wxa[0][j] + G[0][j] + bu_s[j]);
                const float ii   = sigf(wxa[1][j] + G[1][j] + bu_s[4 + j]);
                const float oo   = sigf(wxa[2][j] + G[2][j] + bu_s[8 + j]);
                const float gg   = tanhf(wxa[3][j] + G[3][j] + bu_s[12 + j]);
                const float cn   = ff * cadj + ii * gg;
                const float hn   = oo * tanhf(cn);
                cv[j] = cn; hv[j] = hn;
                stn[(size_t)(cid * 4 + j) * 128 + b] = make_float2(hn, cn);
            }

            const size_t ob = ((size_t)b * Sn + s) * Hn + cid * 4;
            *reinterpret_cast<float4*>(hs_out + ob) = make_float4(hv[0], hv[1], hv[2], hv[3]);
            *reinterpret_cast<float4*>(cs_out + ob) = make_float4(cv[0], cv[1], cv[2], cv[3]);
        }
    }
}

// ---------------------------------------------------------------------------
// Launch
// ---------------------------------------------------------------------------
extern "C" void kernel_launch(void* const* d_in, const int* in_sizes, int n_in,
                              void* d_out, int out_size)
{
    const float* inputs     = (const float*)d_in[0];
    const float* time_diffs = (const float*)d_in[1];
    // d_in[2] = seq_lens (unused by reference)
    const float* W_all      = (const float*)d_in[3];
    const float* b_all      = (const float*)d_in[4];
    const float* U_all      = (const float*)d_in[5];
    const float* b_u        = (const float*)d_in[6];
    const float* W_d        = (const float*)d_in[7];
    const float* b_d        = (const float*)d_in[8];
    const float* W_out      = (const float*)d_in[9];
    const float* b_out      = (const float*)d_in[10];

    float* out = (float*)d_out;                        // [B,S,O]
    float* hs  = out + (size_t)Bn * Sn * On;           // [B,S,H]
    float* cs  = hs  + (size_t)Bn * Sn * Hn;           // [B,S,H]

    const int M = Bn * Sn;  // 65536

    // GEMM1: Wx = inputs @ W_all + b_all  -> g_wx
    {
        dim3 grid((4 * Hn) / 128, M / 128);
        sgemm_bias<<<grid, 256>>>(inputs, W_all, b_all, nullptr, M, 4 * Hn, Dn);
    }

    // Recurrence: persistent grid, grid-wide barrier per step
    {
        const int shmem = 5120 * 8 + 2560 * 4 + 20 * 4;  // 51280 B
        cudaFuncSetAttribute(tlstm_recur,
                             cudaFuncAttributeMaxDynamicSharedMemorySize, shmem);
        tlstm_recur<<<NCTA, 256, shmem>>>(U_all, b_u, W_d, b_d, time_diffs, hs, cs);
    }

    // GEMM2: outputs = hs @ W_out + b_out
    {
        dim3 grid(On / 128, M / 128);
        sgemm_bias<<<grid, 256>>>(hs, W_out, b_out, out, M, On, Hn);
    }
}

// round 9
// speedup vs baseline: 2.4816x; 1.0030x over previous
#include <cuda_runtime.h>
#include <cstddef>

#define Bn 128
#define Sn 512
#define Dn 256
#define Hn 512
#define On 256
#define NCTA 128

// ---------------------------------------------------------------------------
// Device scratch (static __device__ globals — the sanctioned no-alloc scratch)
// ---------------------------------------------------------------------------
__device__ __align__(16) float g_wx[(size_t)Bn * Sn * 4 * Hn];   // [b*S+s][4H]
__device__ __align__(16) float g_state[2 * Hn * Bn * 2];         // ping-pong, float2(h,c), k-major
__device__ unsigned g_count = 0;
__device__ unsigned g_sense = 0;

// ---------------------------------------------------------------------------
// SGEMM with bias: C[M,N] = A[M,K] @ B[K,N] + bias[N]   (unchanged, passing)
// ---------------------------------------------------------------------------
__global__ void __launch_bounds__(256)
sgemm_bias(const float* __restrict__ A, const float* __restrict__ Bm,
           const float* __restrict__ bias, float* __restrict__ C,
           int M, int N, int K)
{
    if (C == nullptr) C = g_wx;

    __shared__ float As[16][132];
    __shared__ float Bs[16][132];

    const int tid = threadIdx.x;
    const int tx = tid & 15;
    const int ty = tid >> 4;
    const int m0 = blockIdx.y * 128;
    const int n0 = blockIdx.x * 128;

    float acc[8][8];
#pragma unroll
    for (int i = 0; i < 8; i++)
#pragma unroll
        for (int j = 0; j < 8; j++) acc[i][j] = 0.0f;

    const int ar = tid >> 1;
    const int ah = tid & 1;
    const float* Abase = A + (size_t)(m0 + ar) * K + ah * 8;
    const int bk = tid >> 5;
    const int bc = (tid & 31) * 4;

    for (int k0 = 0; k0 < K; k0 += 16) {
        float4 a0 = *reinterpret_cast<const float4*>(Abase + k0);
        float4 a1 = *reinterpret_cast<const float4*>(Abase + k0 + 4);
        As[ah * 8 + 0][ar] = a0.x; As[ah * 8 + 1][ar] = a0.y;
        As[ah * 8 + 2][ar] = a0.z; As[ah * 8 + 3][ar] = a0.w;
        As[ah * 8 + 4][ar] = a1.x; As[ah * 8 + 5][ar] = a1.y;
        As[ah * 8 + 6][ar] = a1.z; As[ah * 8 + 7][ar] = a1.w;
#pragma unroll
        for (int p = 0; p < 16; p += 8) {
            float4 bv = *reinterpret_cast<const float4*>(
                Bm + (size_t)(k0 + bk + p) * N + n0 + bc);
            *reinterpret_cast<float4*>(&Bs[bk + p][bc]) = bv;
        }
        __syncthreads();

#pragma unroll
        for (int k = 0; k < 16; k++) {
            float ra[8], rb[8];
            *reinterpret_cast<float4*>(ra)     = *reinterpret_cast<const float4*>(&As[k][ty * 8]);
            *reinterpret_cast<float4*>(ra + 4) = *reinterpret_cast<const float4*>(&As[k][ty * 8 + 4]);
            *reinterpret_cast<float4*>(rb)     = *reinterpret_cast<const float4*>(&Bs[k][tx * 8]);
            *reinterpret_cast<float4*>(rb + 4) = *reinterpret_cast<const float4*>(&Bs[k][tx * 8 + 4]);
#pragma unroll
            for (int i = 0; i < 8; i++)
#pragma unroll
                for (int j = 0; j < 8; j++)
                    acc[i][j] = fmaf(ra[i], rb[j], acc[i][j]);
        }
        __syncthreads();
    }

    float bb[8];
#pragma unroll
    for (int j = 0; j < 8; j++) bb[j] = bias[n0 + tx * 8 + j];

#pragma unroll
    for (int i = 0; i < 8; i++) {
        const size_t row = (size_t)(m0 + ty * 8 + i) * N + n0 + tx * 8;
        float4 o0, o1;
        o0.x = acc[i][0] + bb[0]; o0.y = acc[i][1] + bb[1];
        o0.z = acc[i][2] + bb[2]; o0.w = acc[i][3] + bb[3];
        o1.x = acc[i][4] + bb[4]; o1.y = acc[i][5] + bb[5];
        o1.z = acc[i][6] + bb[6]; o1.w = acc[i][7] + bb[7];
        *reinterpret_cast<float4*>(&C[row])     = o0;
        *reinterpret_cast<float4*>(&C[row + 4]) = o1;
    }
}

// ---------------------------------------------------------------------------
// f32x2 packed helpers (sm_103a)
// ---------------------------------------------------------------------------
__device__ __forceinline__ unsigned long long pack2(float v) {
    unsigned long long r;
    asm("mov.b64 %0, {%1, %1};" : "=l"(r) : "f"(v));
    return r;
}
__device__ __forceinline__ void fma2(unsigned long long& d,
                                     unsigned long long a, unsigned long long b) {
    asm("fma.rn.f32x2 %0, %1, %2, %0;" : "+l"(d) : "l"(a), "l"(b));
}
__device__ __forceinline__ float2 unpack2(unsigned long long v) {
    float2 r;
    asm("mov.b64 {%0, %1}, %2;" : "=f"(r.x), "=f"(r.y) : "l"(v));
    return r;
}

__device__ __forceinline__ float sigf(float x) { return 1.0f / (1.0f + __expf(-x)); }

__device__ __forceinline__ void grid_barrier(unsigned& lsense)
{
    __threadfence();
    __syncthreads();
    if (threadIdx.x == 0) {
        const unsigned target = lsense ^ 1u;
        if (atomicAdd(&g_count, 1u) == (unsigned)(NCTA - 1)) {
            g_count = 0;
            __threadfence();
            *((volatile unsigned*)&g_sense) = target;
        } else {
            while (*((volatile unsigned*)&g_sense) != target) { }
        }
    }
    __syncthreads();
    lsense ^= 1u;
}

// ---------------------------------------------------------------------------
// Persistent recurrence: 128 CTAs x 256 threads.
// CTA cid owns hidden columns j = cid*4 .. cid*4+3.
// Thread = (b = tid&127, kg = tid>>7) computes all 4 j over its K-half with
// f32x2-packed FMAs. State loads are chunked + double-buffered (MLP=16) so
// the ~300-cycle L2 latency is fully covered by each chunk's 160 FFMA2s.
// ---------------------------------------------------------------------------

// Load one 16-k chunk of state (float2 h,c per k) into a register buffer.
#define LOAD_CHUNK(BUF, CH) do {                                          \
    const int kn_ = kb0 + (CH) * 16;                                      \
    _Pragma("unroll")                                                     \
    for (int i_ = 0; i_ < 16; i_++)                                       \
        BUF[i_] = __ldcg(st + (size_t)(kn_ + i_) * 128 + b);              \
} while (0)

// Consume one 16-k chunk: 8 k-pairs x 20 fma2.
#define COMPUTE_CHUNK(BUF, CH) do {                                       \
    _Pragma("unroll")                                                     \
    for (int t_ = 0; t_ < 8; t_++) {                                      \
        const int kp_ = kp0 + (CH) * 8 + t_;                              \
        const unsigned long long hh0 = pack2(BUF[2 * t_].x);              \
        const unsigned long long cc0 = pack2(BUF[2 * t_].y);              \
        const unsigned long long hh1 = pack2(BUF[2 * t_ + 1].x);          \
        const unsigned long long cc1 = pack2(BUF[2 * t_ + 1].y);          \
        _Pragma("unroll")                                                 \
        for (int g_ = 0; g_ < 4; g_++) {                                  \
            _Pragma("unroll")                                             \
            for (int p_ = 0; p_ < 2; p_++) {                              \
                ulonglong2 w = *reinterpret_cast<const ulonglong2*>(      \
                    Us2 + (size_t)(((g_ * 2 + p_) * 256 + kp_) * 2));     \
                fma2(acc[g_ * 2 + p_], hh0, w.x);                         \
                fma2(acc[g_ * 2 + p_], hh1, w.y);                         \
            }                                                             \
        }                                                                 \
        _Pragma("unroll")                                                 \
        for (int p_ = 0; p_ < 2; p_++) {                                  \
            ulonglong2 w = *reinterpret_cast<const ulonglong2*>(          \
                Wd2 + (size_t)((p_ * 256 + kp_) * 2));                    \
            fma2(acc[8 + p_], cc0, w.x);                                  \
            fma2(acc[8 + p_], cc1, w.y);                                  \
        }                                                                 \
    }                                                                     \
} while (0)

__global__ void __launch_bounds__(256, 1)
tlstm_recur(const float* __restrict__ U_all, const float* __restrict__ b_u,
            const float* __restrict__ W_d,  const float* __restrict__ b_d,
            const float* __restrict__ td,
            float* __restrict__ hs_out, float* __restrict__ cs_out)
{
    extern __shared__ unsigned long long smem_u[];
    unsigned long long* Us2 = smem_u;          // [ (g*2+p)*256 + kp ] x {k-even,k-odd} : 4096 ull
    unsigned long long* Wd2 = smem_u + 4096;   // [ p*256 + kp ] x {k-even,k-odd}       : 1024 ull
    float* red  = (float*)(smem_u + 5120);     // [b][20] partials : 2560 floats
    float* bu_s = red + 2560;                  // [g*4 + j] : 16
    float* bd_s = bu_s + 16;                   // [j] : 4

    const int tid = threadIdx.x;
    const int cid = blockIdx.x;
    const int b   = tid & 127;
    const int kg  = tid >> 7;          // which K-half

    // ---- one-time staging: packed weight pairs into SMEM ----
    {
        float* UsF = (float*)Us2;
        for (int i = tid; i < 8192; i += 256) {
            const int jj = i & 1;
            const int h  = (i >> 1) & 1;
            const int kp = (i >> 2) & 255;
            const int p  = (i >> 10) & 1;
            const int g  = i >> 11;
            const int k  = kp * 2 + h;
            UsF[i] = U_all[(size_t)k * 2048 + g * 512 + cid * 4 + p * 2 + jj];
        }
        float* WdF = (float*)Wd2;
        for (int i = tid; i < 2048; i += 256) {
            const int jj = i & 1;
            const int h  = (i >> 1) & 1;
            const int kp = (i >> 2) & 255;
            const int p  = i >> 10;
            const int k  = kp * 2 + h;
            WdF[i] = W_d[(size_t)k * 512 + cid * 4 + p * 2 + jj];
        }
        if (tid < 16) bu_s[tid] = b_u[(tid >> 2) * 512 + cid * 4 + (tid & 3)];
        if (tid < 4)  bd_s[tid] = b_d[cid * 4 + tid];
    }

    // zero ping buffer 0 (disjoint slice per CTA)
    {
        float2* stz = reinterpret_cast<float2*>(g_state);
        for (int i = tid; i < 512; i += 256)
            stz[cid * 512 + i] = make_float2(0.f, 0.f);
    }

    unsigned lsense = *((volatile unsigned*)&g_sense);
    grid_barrier(lsense);

    const int kp0 = kg * 128;          // first k-pair of this thread's half
    const int kb0 = kp0 * 2;           // first k

    for (int s = 0; s < Sn; s++) {
        if (s) grid_barrier(lsense);

        const float2* st = reinterpret_cast<const float2*>(g_state) + (size_t)(s & 1) * (Hn * Bn);
        float2*      stn = reinterpret_cast<float2*>(g_state) + (size_t)((s & 1) ^ 1) * (Hn * Bn);

        // ---- prefetch step operands (consumed after the dot loop) ----
        const float* wxb = g_wx + ((size_t)b * Sn + s) * 2048 + cid * 4;
        float wxa[4][4];
#pragma unroll
        for (int g = 0; g < 4; g++) {
            float4 v = __ldg(reinterpret_cast<const float4*>(wxb + g * 512));
            wxa[g][0] = v.x; wxa[g][1] = v.y; wxa[g][2] = v.z; wxa[g][3] = v.w;
        }
        float c_old[4];
#pragma unroll
        for (int j = 0; j < 4; j++)
            c_old[j] = __ldcg(st + (size_t)(cid * 4 + j) * 128 + b).y;
        const float tdv = __ldg(td + (size_t)b * Sn + s);

        // ---- dot products over this thread's K-half (chunked, MLP=16) ----
        unsigned long long acc[10];
#pragma unroll
        for (int i = 0; i < 10; i++) acc[i] = 0ull;

        float2 bufA[16], bufB[16];
        LOAD_CHUNK(bufA, 0);

#pragma unroll 1
        for (int ch = 0; ch < 16; ch += 2) {
            LOAD_CHUNK(bufB, ch + 1);
            COMPUTE_CHUNK(bufA, ch);
            if (ch + 2 < 16) LOAD_CHUNK(bufA, ch + 2);
            COMPUTE_CHUNK(bufB, ch + 1);
        }

        // ---- reduce the two K-halves via SMEM ----
        if (kg == 1) {
#pragma unroll
            for (int i = 0; i < 10; i++) {
                float2 r = unpack2(acc[i]);
                red[b * 20 + i * 2]     = r.x;
                red[b * 20 + i * 2 + 1] = r.y;
            }
        }
        __syncthreads();

        if (kg == 0) {
            float G[5][4];
#pragma unroll
            for (int i = 0; i < 10; i++) {
                float2 mine = unpack2(acc[i]);
                const int g = i >> 1;
                const int p = i & 1;
                G[g][p * 2 + 0] = mine.x + red[b * 20 + i * 2];
                G[g][p * 2 + 1] = mine.y + red[b * 20 + i * 2 + 1];
            }

            float hv[4], cv[4];
#pragma unroll
            for (int j = 0; j < 4; j++) {
                const float cst  = sigf(G[4][j] + bd_s[j]);
                const float cadj = c_old[j] - cst + cst * tdv;
                const float ff   = sigf(wxa[0][j] + G[0][j] + bu_s[j]);
                const float ii   = sigf(wxa[1][j] + G[1][j] + bu_s[4 + j]);
                const float oo   = sigf(wxa[2][j] + G[2][j] + bu_s[8 + j]);
                const float gg   = tanhf(wxa[3][j] + G[3][j] + bu_s[12 + j]);
                const float cn   = ff * cadj + ii * gg;
                const float hn   = oo * tanhf(cn);
                cv[j] = cn; hv[j] = hn;
                stn[(size_t)(cid * 4 + j) * 128 + b] = make_float2(hn, cn);
            }

            const size_t ob = ((size_t)b * Sn + s) * Hn + cid * 4;
            *reinterpret_cast<float4*>(hs_out + ob) = make_float4(hv[0], hv[1], hv[2], hv[3]);
            *reinterpret_cast<float4*>(cs_out + ob) = make_float4(cv[0], cv[1], cv[2], cv[3]);
        }
    }
}

// ---------------------------------------------------------------------------
// Launch
// ---------------------------------------------------------------------------
extern "C" void kernel_launch(void* const* d_in, const int* in_sizes, int n_in,
                              void* d_out, int out_size)
{
    const float* inputs     = (const float*)d_in[0];
    const float* time_diffs = (const float*)d_in[1];
    // d_in[2] = seq_lens (unused by reference)
    const float* W_all      = (const float*)d_in[3];
    const float* b_all      = (const float*)d_in[4];
    const float* U_all      = (const float*)d_in[5];
    const float* b_u        = (const float*)d_in[6];
    const float* W_d        = (const float*)d_in[7];
    const float* b_d        = (const float*)d_in[8];
    const float* W_out      = (const float*)d_in[9];
    const float* b_out      = (const float*)d_in[10];

    float* out = (float*)d_out;                        // [B,S,O]
    float* hs  = out + (size_t)Bn * Sn * On;           // [B,S,H]
    float* cs  = hs  + (size_t)Bn * Sn * Hn;           // [B,S,H]

    const int M = Bn * Sn;  // 65536

    // GEMM1: Wx = inputs @ W_all + b_all  -> g_wx
    {
        dim3 grid((4 * Hn) / 128, M / 128);
        sgemm_bias<<<grid, 256>>>(inputs, W_all, b_all, nullptr, M, 4 * Hn, Dn);
    }

    // Recurrence: persistent grid, grid-wide barrier per step
    {
        const int shmem = 5120 * 8 + 2560 * 4 + 20 * 4;  // 51280 B
        cudaFuncSetAttribute(tlstm_recur,
                             cudaFuncAttributeMaxDynamicSharedMemorySize, shmem);
        tlstm_recur<<<NCTA, 256, shmem>>>(U_all, b_u, W_d, b_d, time_diffs, hs, cs);
    }

    // GEMM2: outputs = hs @ W_out + b_out
    {
        dim3 grid(On / 128, M / 128);
        sgemm_bias<<<grid, 256>>>(hs, W_out, b_out, out, M, On, Hn);
    }
}